// round 8
// baseline (speedup 1.0000x reference)
#include <cuda_runtime.h>
#include <cstdint>
#include <math.h>

#define Bz   32
#define SQ   2048
#define SKV  2048
#define Dd   128
#define BM   64
#define BN   128
#define NT   512

#define QS 68      // sQt stride [d][row64]
#define KS 132     // sKt stride [d][kv128]
#define VS 132     // sV  stride [n][d128]
#define PS 68      // sPt stride [col128][row64]

typedef unsigned long long u64;
typedef unsigned int u32;

// 32 MB static: K pre-transposed to [B][D][SKV]
__device__ float g_kt[(size_t)Bz * Dd * SKV];

// ---------------- f32x2 packed helpers ----------------
__device__ __forceinline__ u64 ffma2(u64 a, u64 b, u64 c) {
    u64 d; asm("fma.rn.f32x2 %0, %1, %2, %3;" : "=l"(d) : "l"(a), "l"(b), "l"(c));
    return d;
}
__device__ __forceinline__ u64 fmul2(u64 a, u64 b) {
    u64 d; asm("mul.rn.f32x2 %0, %1, %2;" : "=l"(d) : "l"(a), "l"(b));
    return d;
}
__device__ __forceinline__ u64 pk2(float lo, float hi) {
    u64 d; asm("mov.b64 %0, {%1, %2};" : "=l"(d)
               : "r"(__float_as_uint(lo)), "r"(__float_as_uint(hi)));
    return d;
}
__device__ __forceinline__ void upk2(u64 v, float& lo, float& hi) {
    u32 a, b; asm("mov.b64 {%0, %1}, %2;" : "=r"(a), "=r"(b) : "l"(v));
    lo = __uint_as_float(a); hi = __uint_as_float(b);
}

// ---------------- cp.async helpers ----------------
__device__ __forceinline__ void cpa16(u32 dst, const float* src) {
    asm volatile("cp.async.cg.shared.global [%0], [%1], 16;" :: "r"(dst), "l"(src));
}
#define CP_COMMIT() asm volatile("cp.async.commit_group;" ::: "memory")
#define CP_WAIT0()  asm volatile("cp.async.wait_group 0;" ::: "memory")
#define CP_WAIT1()  asm volatile("cp.async.wait_group 1;" ::: "memory")

// ---------------- Threefry-2x32-20, key=(0,42) ----------------
__device__ __forceinline__ void threefry_0_42(u32 x0, u32 x1, u32& y0, u32& y1) {
    const u32 ks1 = 42u;
    const u32 ks2 = 0x1BD11BDAu ^ 42u;
    x1 += ks1;
#define TF_R(r) { x0 += x1; x1 = __funnelshift_l(x1, x1, (r)); x1 ^= x0; }
    TF_R(13) TF_R(15) TF_R(26) TF_R(6)
    x0 += ks1; x1 += ks2 + 1u;
    TF_R(17) TF_R(29) TF_R(16) TF_R(24)
    x0 += ks2; x1 += 2u;
    TF_R(13) TF_R(15) TF_R(26) TF_R(6)
    x0 += 0u;  x1 += ks1 + 3u;
    TF_R(17) TF_R(29) TF_R(16) TF_R(24)
    x0 += ks1; x1 += ks2 + 4u;
    TF_R(13) TF_R(15) TF_R(26) TF_R(6)
    x0 += ks2; x1 += 5u;
#undef TF_R
    y0 = x0; y1 = x1;
}
// keep <=> fp32-uniform(bits) < 0.7  <=>  bits < (5872026 << 9)   (exact)
#define KEEP_THRESH 3006477312u

// ---------------------------------------------------------------------------
// K transpose: g_kt[b][d][s] = k[b][s][d]
// ---------------------------------------------------------------------------
__global__ __launch_bounds__(256, 4) void transpose_k_kernel(const float* __restrict__ k) {
    __shared__ float t[32][33];
    int b  = blockIdx.z;
    int s0 = blockIdx.x << 5;
    int d0 = blockIdx.y << 5;
    const float* kb = k + ((size_t)b * SKV + s0) * Dd + d0;
#pragma unroll
    for (int r = threadIdx.y; r < 32; r += 8)
        t[r][threadIdx.x] = kb[r * Dd + threadIdx.x];
    __syncthreads();
    float* kt = g_kt + ((size_t)b * Dd + d0) * SKV + s0;
#pragma unroll
    for (int r = threadIdx.y; r < 32; r += 8)
        kt[r * SKV + threadIdx.x] = t[threadIdx.x][r];
}

// ---------------------------------------------------------------------------
// Flash attention, fp32 FFMA2, cp.async K/V pipeline, 512 threads (4 w/SMSP).
// CTA = (batch b, 64 q rows). tm = tid>>5 (0..15), tn = tid&31.
// Thread: S rows 4tm+i (i<4), S cols 4tn+j (j<4); O cols 4tn+j.
// ---------------------------------------------------------------------------
__global__ __launch_bounds__(NT, 1) void attn_kernel(
    const float* __restrict__ q, const float* __restrict__ v,
    const float* __restrict__ sf, float* __restrict__ out) {

    extern __shared__ float sm[];
    float* sQt = sm;                    // [128][QS]
    float* sKt = sQt + Dd * QS;         // [128][KS]  d-major, from g_kt
    float* sV  = sKt + Dd * KS;         // [128][VS]
    float* sPt = sV + BN * VS;          // [128][PS]  P^T masked

    const int tid = threadIdx.x;
    const int tm  = tid >> 5;           // 0..15
    const int tn  = tid & 31;           // 0..31
    const int b   = blockIdx.y;
    const int q0  = blockIdx.x * BM;
    const float scale = sf[b];

    const float* ktb = g_kt + (size_t)b * Dd * SKV;     // [d][s]
    const float* vb  = v + (size_t)b * SKV * Dd;        // [s][d]

    // ---- prologue: start K(0) copy ----
    {
        u32 dK = (u32)__cvta_generic_to_shared(sKt);
#pragma unroll
        for (int it = 0; it < 8; ++it) {
            int id = it * NT + tid;             // 0..4095
            int d  = id >> 5;                   // 0..127
            int c  = (id & 31) << 2;            // float offset
            cpa16(dK + (u32)(d * KS + c) * 4u, ktb + (size_t)d * SKV + 0 + c);
        }
        CP_COMMIT();
    }

    // ---- stage Q (once), transposed + pre-scaled ----
    {
        const float* qb = q + ((size_t)b * SQ + q0) * Dd;
#pragma unroll
        for (int it = 0; it < 16; ++it) {
            int idx = it * NT + tid;            // 0..8191
            int r = idx >> 7;                   // 0..63
            int d = idx & 127;
            sQt[d * QS + r] = qb[idx] * scale;
        }
    }

    u64 acc[2][4];
    float m_i[4], l_i[4];
#pragma unroll
    for (int ip = 0; ip < 2; ++ip)
#pragma unroll
        for (int j = 0; j < 4; ++j) acc[ip][j] = 0ull;
#pragma unroll
    for (int i = 0; i < 4; ++i) { m_i[i] = -INFINITY; l_i[i] = 0.f; }

    u32 dV = (u32)__cvta_generic_to_shared(sV);
    u32 dK = (u32)__cvta_generic_to_shared(sKt);

    const u32 eBase0 = ((u32)(b * SQ + q0 + (tm << 2))) * (u32)SKV + (u32)(tn << 2);

    for (int kv0 = 0; kv0 < SKV; kv0 += BN) {
        // K(i) landed (only it may be pending at this point)
        CP_WAIT0();
        __syncthreads();        // K visible to all; prev PV done -> sV free

        // issue V(i); waited before PV (hidden by QK)
        {
#pragma unroll
            for (int it = 0; it < 8; ++it) {
                int id = it * NT + tid;
                int r  = id >> 5;
                int c  = (id & 31) << 2;
                cpa16(dV + (u32)(r * VS + c) * 4u,
                      vb + (size_t)(kv0 + r) * Dd + c);
            }
            CP_COMMIT();
        }

        // ---- S = Q@K^T via FFMA2 ----
        u64 s2[2][4];
#pragma unroll
        for (int ip = 0; ip < 2; ++ip)
#pragma unroll
            for (int j = 0; j < 4; ++j) s2[ip][j] = 0ull;

#pragma unroll 4
        for (int d = 0; d < Dd; ++d) {
            ulonglong2 qv = *(const ulonglong2*)(sQt + d * QS + (tm << 2));
            u64 q01 = qv.x, q23 = qv.y;
            float4 kf = *(const float4*)(sKt + d * KS + (tn << 2));
            u64 k0 = pk2(kf.x, kf.x), k1 = pk2(kf.y, kf.y);
            u64 k2 = pk2(kf.z, kf.z), k3 = pk2(kf.w, kf.w);
            s2[0][0] = ffma2(q01, k0, s2[0][0]);
            s2[0][1] = ffma2(q01, k1, s2[0][1]);
            s2[0][2] = ffma2(q01, k2, s2[0][2]);
            s2[0][3] = ffma2(q01, k3, s2[0][3]);
            s2[1][0] = ffma2(q23, k0, s2[1][0]);
            s2[1][1] = ffma2(q23, k1, s2[1][1]);
            s2[1][2] = ffma2(q23, k2, s2[1][2]);
            s2[1][3] = ffma2(q23, k3, s2[1][3]);
        }

        // ---- online softmax (4 rows) ----
        float p[4][4];
#pragma unroll
        for (int ip = 0; ip < 2; ++ip)
#pragma unroll
            for (int j = 0; j < 4; ++j)
                upk2(s2[ip][j], p[2 * ip][j], p[2 * ip + 1][j]);

        float fac[4];
#pragma unroll
        for (int i = 0; i < 4; ++i) {
            float mx = fmaxf(fmaxf(p[i][0], p[i][1]), fmaxf(p[i][2], p[i][3]));
#pragma unroll
            for (int off = 16; off >= 1; off >>= 1)
                mx = fmaxf(mx, __shfl_xor_sync(0xffffffffu, mx, off));
            float mnew = fmaxf(m_i[i], mx);
            fac[i] = __expf(m_i[i] - mnew);
            m_i[i] = mnew;
            float rs = 0.f;
#pragma unroll
            for (int j = 0; j < 4; ++j) {
                p[i][j] = __expf(p[i][j] - mnew);
                rs += p[i][j];
            }
#pragma unroll
            for (int off = 16; off >= 1; off >>= 1)
                rs += __shfl_xor_sync(0xffffffffu, rs, off);
            l_i[i] = l_i[i] * fac[i] + rs;
        }
#pragma unroll
        for (int ip = 0; ip < 2; ++ip) {
            u64 f2 = pk2(fac[2 * ip], fac[2 * ip + 1]);
#pragma unroll
            for (int j = 0; j < 4; ++j) acc[ip][j] = fmul2(acc[ip][j], f2);
        }

        // ---- inline dropout mask (jax partitionable threefry, key 42) ----
        u32 mbits = 0;                          // bit (i*4+j) = keep p[i][j]
        {
            const u32 eBase = eBase0 + (u32)kv0;
#pragma unroll
            for (int i = 0; i < 4; ++i) {
                u32 eRow = eBase + ((u32)i << 11);
#pragma unroll
                for (int j = 0; j < 4; ++j) {
                    u32 y0, y1;
                    threefry_0_42(0u, eRow + (u32)j, y0, y1);
                    mbits |= (u32)((y0 ^ y1) < KEEP_THRESH) << (i * 4 + j);
                }
            }
        }

        // ---- write masked P^T ----
#pragma unroll
        for (int j = 0; j < 4; ++j) {
            int c = (tn << 2) + j;
            float4 w;
            w.x = (mbits >> (0 + j)) & 1u  ? p[0][j] : 0.f;
            w.y = (mbits >> (4 + j)) & 1u  ? p[1][j] : 0.f;
            w.z = (mbits >> (8 + j)) & 1u  ? p[2][j] : 0.f;
            w.w = (mbits >> (12 + j)) & 1u ? p[3][j] : 0.f;
            *(float4*)(sPt + c * PS + (tm << 2)) = w;
        }
        __syncthreads();        // all QK reads of sKt done; P visible

        // issue K(i+1) into sKt (hidden by PV)
        if (kv0 + BN < SKV) {
#pragma unroll
            for (int it = 0; it < 8; ++it) {
                int id = it * NT + tid;
                int d  = id >> 5;
                int c  = (id & 31) << 2;
                cpa16(dK + (u32)(d * KS + c) * 4u,
                      ktb + (size_t)d * SKV + (kv0 + BN) + c);
            }
            CP_COMMIT();
            CP_WAIT1();         // V(i) done; K(i+1) may fly
        } else {
            CP_WAIT0();         // V(i) done
        }
        __syncthreads();        // V visible to all

        // ---- acc += P^T' @ V via FFMA2 ----
#pragma unroll 4
        for (int n = 0; n < BN; ++n) {
            ulonglong2 pA = *(const ulonglong2*)(sPt + n * PS + (tm << 2));
            u64 p01 = pA.x, p23 = pA.y;
            float4 vf = *(const float4*)(sV + n * VS + (tn << 2));
            u64 v0 = pk2(vf.x, vf.x), v1 = pk2(vf.y, vf.y);
            u64 v2 = pk2(vf.z, vf.z), v3 = pk2(vf.w, vf.w);
            acc[0][0] = ffma2(p01, v0, acc[0][0]);
            acc[0][1] = ffma2(p01, v1, acc[0][1]);
            acc[0][2] = ffma2(p01, v2, acc[0][2]);
            acc[0][3] = ffma2(p01, v3, acc[0][3]);
            acc[1][0] = ffma2(p23, v0, acc[1][0]);
            acc[1][1] = ffma2(p23, v1, acc[1][1]);
            acc[1][2] = ffma2(p23, v2, acc[1][2]);
            acc[1][3] = ffma2(p23, v3, acc[1][3]);
        }
    }

    // ---- epilogue: out = acc / (l * 0.7) ----
#pragma unroll
    for (int ip = 0; ip < 2; ++ip) {
        float inv0 = 1.0f / (l_i[2 * ip] * 0.7f);
        float inv1 = 1.0f / (l_i[2 * ip + 1] * 0.7f);
        float lo[4], hi[4];
#pragma unroll
        for (int j = 0; j < 4; ++j) upk2(acc[ip][j], lo[j], hi[j]);
        int r0 = q0 + (tm << 2) + 2 * ip;
        float* o0 = out + ((size_t)b * SQ + r0) * Dd + (tn << 2);
        float* o1 = o0 + Dd;
        *(float4*)o0 = make_float4(lo[0] * inv0, lo[1] * inv0, lo[2] * inv0, lo[3] * inv0);
        *(float4*)o1 = make_float4(hi[0] * inv1, hi[1] * inv1, hi[2] * inv1, hi[3] * inv1);
    }
}

// ---------------------------------------------------------------------------
extern "C" void kernel_launch(void* const* d_in, const int* in_sizes, int n_in,
                              void* d_out, int out_size) {
    const float* q  = (const float*)d_in[0];
    const float* k  = (const float*)d_in[1];
    const float* v  = (const float*)d_in[2];
    const float* sf = (const float*)d_in[3];
    float* out = (float*)d_out;

    // 1) K -> g_kt transpose  [B][D][SKV]
    {
        dim3 grid(SKV / 32, Dd / 32, Bz);
        transpose_k_kernel<<<grid, dim3(32, 8)>>>(k);
    }

    // 2) Flash attention
    size_t smem_bytes = (size_t)(Dd * QS + Dd * KS + BN * VS + BN * PS) * 4;
    cudaFuncSetAttribute(attn_kernel, cudaFuncAttributeMaxDynamicSharedMemorySize,
                         (int)smem_bytes);
    dim3 grid(SQ / BM, Bz);
    attn_kernel<<<grid, NT, smem_bytes>>>(q, v, sf, out);
}

// round 9
// speedup vs baseline: 1.0529x; 1.0529x over previous
#include <cuda_runtime.h>
#include <cstdint>
#include <math.h>

#define Bz   32
#define SQ   2048
#define SKV  2048
#define Dd   128
#define BM   64
#define BN   128
#define NT   384          // 256 compute + 128 mask-producer
#define NC   256          // compute threads

#define QS 68      // sQt stride [d][row64]
#define KS 132     // sKt stride [d][kv128]
#define VS 132     // sV  stride [n][d128]
#define PS 68      // sPt stride [col128][row64]

typedef unsigned long long u64;
typedef unsigned int u32;

// 32 MB static: K pre-transposed to [B][D][SKV]
__device__ float g_kt[(size_t)Bz * Dd * SKV];

// ---------------- f32x2 packed helpers ----------------
__device__ __forceinline__ u64 ffma2(u64 a, u64 b, u64 c) {
    u64 d; asm("fma.rn.f32x2 %0, %1, %2, %3;" : "=l"(d) : "l"(a), "l"(b), "l"(c));
    return d;
}
__device__ __forceinline__ u64 fmul2(u64 a, u64 b) {
    u64 d; asm("mul.rn.f32x2 %0, %1, %2;" : "=l"(d) : "l"(a), "l"(b));
    return d;
}
__device__ __forceinline__ u64 pk2(float lo, float hi) {
    u64 d; asm("mov.b64 %0, {%1, %2};" : "=l"(d)
               : "r"(__float_as_uint(lo)), "r"(__float_as_uint(hi)));
    return d;
}
__device__ __forceinline__ void upk2(u64 v, float& lo, float& hi) {
    u32 a, b; asm("mov.b64 {%0, %1}, %2;" : "=r"(a), "=r"(b) : "l"(v));
    lo = __uint_as_float(a); hi = __uint_as_float(b);
}

// ---------------- cp.async helpers ----------------
__device__ __forceinline__ void cpa16(u32 dst, const float* src) {
    asm volatile("cp.async.cg.shared.global [%0], [%1], 16;" :: "r"(dst), "l"(src));
}
#define CP_COMMIT() asm volatile("cp.async.commit_group;" ::: "memory")
#define CP_WAIT0()  asm volatile("cp.async.wait_group 0;" ::: "memory")
#define CP_WAIT1()  asm volatile("cp.async.wait_group 1;" ::: "memory")

// ---------------- Threefry-2x32-20, key=(0,42) ----------------
__device__ __forceinline__ void threefry_0_42(u32 x0, u32 x1, u32& y0, u32& y1) {
    const u32 ks1 = 42u;
    const u32 ks2 = 0x1BD11BDAu ^ 42u;
    x1 += ks1;
#define TF_R(r) { x0 += x1; x1 = __funnelshift_l(x1, x1, (r)); x1 ^= x0; }
    TF_R(13) TF_R(15) TF_R(26) TF_R(6)
    x0 += ks1; x1 += ks2 + 1u;
    TF_R(17) TF_R(29) TF_R(16) TF_R(24)
    x0 += ks2; x1 += 2u;
    TF_R(13) TF_R(15) TF_R(26) TF_R(6)
    x0 += 0u;  x1 += ks1 + 3u;
    TF_R(17) TF_R(29) TF_R(16) TF_R(24)
    x0 += ks1; x1 += ks2 + 4u;
    TF_R(13) TF_R(15) TF_R(26) TF_R(6)
    x0 += ks2; x1 += 5u;
#undef TF_R
    y0 = x0; y1 = x1;
}
// keep <=> fp32-uniform(bits) < 0.7  <=>  bits < (5872026 << 9)   (exact)
#define KEEP_THRESH 3006477312u

// ---------------------------------------------------------------------------
// K transpose: g_kt[b][d][s] = k[b][s][d]
// ---------------------------------------------------------------------------
__global__ __launch_bounds__(256, 4) void transpose_k_kernel(const float* __restrict__ k) {
    __shared__ float t[32][33];
    int b  = blockIdx.z;
    int s0 = blockIdx.x << 5;
    int d0 = blockIdx.y << 5;
    const float* kb = k + ((size_t)b * SKV + s0) * Dd + d0;
#pragma unroll
    for (int r = threadIdx.y; r < 32; r += 8)
        t[r][threadIdx.x] = kb[r * Dd + threadIdx.x];
    __syncthreads();
    float* kt = g_kt + ((size_t)b * Dd + d0) * SKV + s0;
#pragma unroll
    for (int r = threadIdx.y; r < 32; r += 8)
        kt[r * SKV + threadIdx.x] = t[threadIdx.x][r];
}

// ---------------------------------------------------------------------------
// Mask tile producer (device helper): compute the 256 keep-words of tile
// `kvt` into sMaskBuf[slot].  mt in [0,128): computes words for compute
// threads 2mt and 2mt+1.  Word layout: bit (i*4+j) = keep(row 8tm+i, col 4tn+j).
// ---------------------------------------------------------------------------
__device__ __forceinline__ void produce_mask_tile(u32* dst, int mt,
                                                  u32 rowBase, u32 kvBase) {
#pragma unroll
    for (int w2 = 0; w2 < 2; ++w2) {
        int ct = 2 * mt + w2;
        int tmc = ct >> 5, tnc = ct & 31;
        u32 eb = (rowBase + ((u32)tmc << 3)) * (u32)SKV + kvBase + ((u32)tnc << 2);
        u32 word = 0;
#pragma unroll
        for (int i = 0; i < 8; ++i) {
            u32 eRow = eb + ((u32)i << 11);
#pragma unroll
            for (int j = 0; j < 4; ++j) {
                u32 y0, y1;
                threefry_0_42(0u, eRow + (u32)j, y0, y1);
                word |= (u32)((y0 ^ y1) < KEEP_THRESH) << (i * 4 + j);
            }
        }
        dst[ct] = word;
    }
}

// ---------------------------------------------------------------------------
// Flash attention, fp32 FFMA2, cp.async K/V pipeline, warp-specialized
// threefry mask producer. CTA = (batch b, 64 q rows).
// Compute threads (tid<256): tm = tid>>5 (0..7), tn = tid&31.
//   S rows 8tm+i (i<8), S cols 4tn+j (j<4); O cols 4tn+j.
// Mask threads (tid>=256): produce keep-words for tile i+1.
// ---------------------------------------------------------------------------
__global__ __launch_bounds__(NT, 1) void attn_kernel(
    const float* __restrict__ q, const float* __restrict__ v,
    const float* __restrict__ sf, float* __restrict__ out) {

    extern __shared__ float sm[];
    float* sQt = sm;                    // [128][QS]
    float* sKt = sQt + Dd * QS;         // [128][KS]  d-major, from g_kt
    float* sV  = sKt + Dd * KS;         // [128][VS]
    float* sPt = sV + BN * VS;          // [128][PS]  P^T masked
    u32*  sMk  = (u32*)(sPt + BN * PS); // [2][256] keep-words, double-buffered

    const int tid = threadIdx.x;
    const int b   = blockIdx.y;
    const int q0  = blockIdx.x * BM;

    const float* ktb = g_kt + (size_t)b * Dd * SKV;     // [d][s]
    const float* vb  = v + (size_t)b * SKV * Dd;        // [s][d]

    const u32 rowBase = (u32)(b * SQ + q0);

    u32 dV = (u32)__cvta_generic_to_shared(sV);
    u32 dK = (u32)__cvta_generic_to_shared(sKt);

    const int tm = tid >> 5;            // compute role (valid when tid<256)
    const int tn = tid & 31;

    if (tid < NC) {
        // ---- prologue: start K(0) copy, stage Q ----
#pragma unroll
        for (int it = 0; it < 16; ++it) {
            int id = it * NC + tid;             // 0..4095
            int d  = id >> 5;
            int c  = (id & 31) << 2;
            cpa16(dK + (u32)(d * KS + c) * 4u, ktb + (size_t)d * SKV + 0 + c);
        }
        CP_COMMIT();
        const float scale = sf[b];
        const float* qb = q + ((size_t)b * SQ + q0) * Dd;
#pragma unroll
        for (int it = 0; it < 32; ++it) {
            int idx = it * NC + tid;
            int r = idx >> 7;
            int d = idx & 127;
            sQt[d * QS + r] = qb[idx] * scale;
        }
    } else {
        // ---- prologue: mask warps produce tile 0 ----
        produce_mask_tile(sMk, tid - NC, rowBase, 0u);
    }

    u64 acc[4][4];
    float m_i[8], l_i[8];
#pragma unroll
    for (int ip = 0; ip < 4; ++ip)
#pragma unroll
        for (int j = 0; j < 4; ++j) acc[ip][j] = 0ull;
#pragma unroll
    for (int i = 0; i < 8; ++i) { m_i[i] = -INFINITY; l_i[i] = 0.f; }

    for (int kv0 = 0; kv0 < SKV; kv0 += BN) {
        const int itn = kv0 / BN;
        CP_WAIT0();             // K(i) landed (no-op for mask warps)
        __syncthreads();        // A: K + mask(i) visible; prev PV done

        if (tid < NC) {
            // issue V(i); waited before PV (hidden by QK)
#pragma unroll
            for (int it = 0; it < 16; ++it) {
                int id = it * NC + tid;
                int r  = id >> 5;
                int c  = (id & 31) << 2;
                cpa16(dV + (u32)(r * VS + c) * 4u,
                      vb + (size_t)(kv0 + r) * Dd + c);
            }
            CP_COMMIT();

            u32 mbits = sMk[(itn & 1) * NC + tid];   // precomputed keep-word

            // ---- S = Q@K^T via FFMA2 ----
            u64 s2[4][4];
#pragma unroll
            for (int ip = 0; ip < 4; ++ip)
#pragma unroll
                for (int j = 0; j < 4; ++j) s2[ip][j] = 0ull;

#pragma unroll 4
            for (int d = 0; d < Dd; ++d) {
                ulonglong2 qv = *(const ulonglong2*)(sQt + d * QS + (tm << 3));
                ulonglong2 qw = *(const ulonglong2*)(sQt + d * QS + (tm << 3) + 4);
                u64 q01 = qv.x, q23 = qv.y, q45 = qw.x, q67 = qw.y;
                float4 kf = *(const float4*)(sKt + d * KS + (tn << 2));
                u64 k0 = pk2(kf.x, kf.x), k1 = pk2(kf.y, kf.y);
                u64 k2 = pk2(kf.z, kf.z), k3 = pk2(kf.w, kf.w);
                s2[0][0] = ffma2(q01, k0, s2[0][0]);
                s2[0][1] = ffma2(q01, k1, s2[0][1]);
                s2[0][2] = ffma2(q01, k2, s2[0][2]);
                s2[0][3] = ffma2(q01, k3, s2[0][3]);
                s2[1][0] = ffma2(q23, k0, s2[1][0]);
                s2[1][1] = ffma2(q23, k1, s2[1][1]);
                s2[1][2] = ffma2(q23, k2, s2[1][2]);
                s2[1][3] = ffma2(q23, k3, s2[1][3]);
                s2[2][0] = ffma2(q45, k0, s2[2][0]);
                s2[2][1] = ffma2(q45, k1, s2[2][1]);
                s2[2][2] = ffma2(q45, k2, s2[2][2]);
                s2[2][3] = ffma2(q45, k3, s2[2][3]);
                s2[3][0] = ffma2(q67, k0, s2[3][0]);
                s2[3][1] = ffma2(q67, k1, s2[3][1]);
                s2[3][2] = ffma2(q67, k2, s2[3][2]);
                s2[3][3] = ffma2(q67, k3, s2[3][3]);
            }

            // ---- online softmax ----
            float p[8][4];
#pragma unroll
            for (int ip = 0; ip < 4; ++ip)
#pragma unroll
                for (int j = 0; j < 4; ++j)
                    upk2(s2[ip][j], p[2 * ip][j], p[2 * ip + 1][j]);

            float fac[8];
#pragma unroll
            for (int i = 0; i < 8; ++i) {
                float mx = fmaxf(fmaxf(p[i][0], p[i][1]), fmaxf(p[i][2], p[i][3]));
#pragma unroll
                for (int off = 16; off >= 1; off >>= 1)
                    mx = fmaxf(mx, __shfl_xor_sync(0xffffffffu, mx, off));
                float mnew = fmaxf(m_i[i], mx);
                fac[i] = __expf(m_i[i] - mnew);
                m_i[i] = mnew;
                float rs = 0.f;
#pragma unroll
                for (int j = 0; j < 4; ++j) {
                    p[i][j] = __expf(p[i][j] - mnew);
                    rs += p[i][j];
                }
#pragma unroll
                for (int off = 16; off >= 1; off >>= 1)
                    rs += __shfl_xor_sync(0xffffffffu, rs, off);
                l_i[i] = l_i[i] * fac[i] + rs;
            }
#pragma unroll
            for (int ip = 0; ip < 4; ++ip) {
                u64 f2 = pk2(fac[2 * ip], fac[2 * ip + 1]);
#pragma unroll
                for (int j = 0; j < 4; ++j) acc[ip][j] = fmul2(acc[ip][j], f2);
            }

            // ---- write masked P^T (apply keep bits) ----
#pragma unroll
            for (int j = 0; j < 4; ++j) {
                int c = (tn << 2) + j;
                float4 w0, w1;
                w0.x = (mbits >> (0 + j)) & 1u  ? p[0][j] : 0.f;
                w0.y = (mbits >> (4 + j)) & 1u  ? p[1][j] : 0.f;
                w0.z = (mbits >> (8 + j)) & 1u  ? p[2][j] : 0.f;
                w0.w = (mbits >> (12 + j)) & 1u ? p[3][j] : 0.f;
                w1.x = (mbits >> (16 + j)) & 1u ? p[4][j] : 0.f;
                w1.y = (mbits >> (20 + j)) & 1u ? p[5][j] : 0.f;
                w1.z = (mbits >> (24 + j)) & 1u ? p[6][j] : 0.f;
                w1.w = (mbits >> (28 + j)) & 1u ? p[7][j] : 0.f;
                *(float4*)(sPt + c * PS + (tm << 3)) = w0;
                *(float4*)(sPt + c * PS + (tm << 3) + 4) = w1;
            }
        } else {
            // ---- mask warps: produce keep-words for tile i+1 ----
            if (kv0 + BN < SKV)
                produce_mask_tile(sMk + ((itn + 1) & 1) * NC, tid - NC,
                                  rowBase, (u32)(kv0 + BN));
        }
        __syncthreads();        // B: QK reads of sKt done; P visible

        if (tid < NC) {
            // issue K(i+1) into sKt (hidden by PV)
            if (kv0 + BN < SKV) {
#pragma unroll
                for (int it = 0; it < 16; ++it) {
                    int id = it * NC + tid;
                    int d  = id >> 5;
                    int c  = (id & 31) << 2;
                    cpa16(dK + (u32)(d * KS + c) * 4u,
                          ktb + (size_t)d * SKV + (kv0 + BN) + c);
                }
                CP_COMMIT();
                CP_WAIT1();     // V(i) done; K(i+1) may fly
            } else {
                CP_WAIT0();     // V(i) done
            }
        }
        __syncthreads();        // C: V visible to all

        if (tid < NC) {
            // ---- acc += P^T' @ V via FFMA2 ----
#pragma unroll 4
            for (int n = 0; n < BN; ++n) {
                ulonglong2 pA = *(const ulonglong2*)(sPt + n * PS + (tm << 3));
                ulonglong2 pB = *(const ulonglong2*)(sPt + n * PS + (tm << 3) + 4);
                u64 p01 = pA.x, p23 = pA.y, p45 = pB.x, p67 = pB.y;
                float4 vf = *(const float4*)(sV + n * VS + (tn << 2));
                u64 v0 = pk2(vf.x, vf.x), v1 = pk2(vf.y, vf.y);
                u64 v2 = pk2(vf.z, vf.z), v3 = pk2(vf.w, vf.w);
                acc[0][0] = ffma2(p01, v0, acc[0][0]);
                acc[0][1] = ffma2(p01, v1, acc[0][1]);
                acc[0][2] = ffma2(p01, v2, acc[0][2]);
                acc[0][3] = ffma2(p01, v3, acc[0][3]);
                acc[1][0] = ffma2(p23, v0, acc[1][0]);
                acc[1][1] = ffma2(p23, v1, acc[1][1]);
                acc[1][2] = ffma2(p23, v2, acc[1][2]);
                acc[1][3] = ffma2(p23, v3, acc[1][3]);
                acc[2][0] = ffma2(p45, v0, acc[2][0]);
                acc[2][1] = ffma2(p45, v1, acc[2][1]);
                acc[2][2] = ffma2(p45, v2, acc[2][2]);
                acc[3][0] = ffma2(p67, v0, acc[3][0]);
                acc[2][3] = ffma2(p45, v3, acc[2][3]);
                acc[3][1] = ffma2(p67, v1, acc[3][1]);
                acc[3][2] = ffma2(p67, v2, acc[3][2]);
                acc[3][3] = ffma2(p67, v3, acc[3][3]);
            }
        }
    }

    // ---- epilogue: out = acc / (l * 0.7) ----
    if (tid < NC) {
#pragma unroll
        for (int ip = 0; ip < 4; ++ip) {
            float inv0 = 1.0f / (l_i[2 * ip] * 0.7f);
            float inv1 = 1.0f / (l_i[2 * ip + 1] * 0.7f);
            float lo[4], hi[4];
#pragma unroll
            for (int j = 0; j < 4; ++j) upk2(acc[ip][j], lo[j], hi[j]);
            int r0 = q0 + (tm << 3) + 2 * ip;
            float* o0 = out + ((size_t)b * SQ + r0) * Dd + (tn << 2);
            float* o1 = o0 + Dd;
            *(float4*)o0 = make_float4(lo[0] * inv0, lo[1] * inv0,
                                       lo[2] * inv0, lo[3] * inv0);
            *(float4*)o1 = make_float4(hi[0] * inv1, hi[1] * inv1,
                                       hi[2] * inv1, hi[3] * inv1);
        }
    }
}

// ---------------------------------------------------------------------------
extern "C" void kernel_launch(void* const* d_in, const int* in_sizes, int n_in,
                              void* d_out, int out_size) {
    const float* q  = (const float*)d_in[0];
    const float* k  = (const float*)d_in[1];
    const float* v  = (const float*)d_in[2];
    const float* sf = (const float*)d_in[3];
    float* out = (float*)d_out;

    // 1) K -> g_kt transpose  [B][D][SKV]
    {
        dim3 grid(SKV / 32, Dd / 32, Bz);
        transpose_k_kernel<<<grid, dim3(32, 8)>>>(k);
    }

    // 2) Flash attention (+2KB for double-buffered mask words)
    size_t smem_bytes = (size_t)(Dd * QS + Dd * KS + BN * VS + BN * PS) * 4
                        + 2 * NC * sizeof(u32);
    cudaFuncSetAttribute(attn_kernel, cudaFuncAttributeMaxDynamicSharedMemorySize,
                         (int)smem_bytes);
    dim3 grid(SQ / BM, Bz);
    attn_kernel<<<grid, NT, smem_bytes>>>(q, v, sf, out);
}

// round 12
// speedup vs baseline: 1.1756x; 1.1165x over previous
#include <cuda_runtime.h>
#include <cstdint>
#include <math.h>

#define Bz   32
#define SQ   2048
#define SKV  2048
#define Dd   128
#define BM   64
#define BN   128
#define NT   256

#define QS 68      // sQt stride [d][row64]
#define KS 132     // sKt stride [d][kv128]
#define VS 132     // sV  stride [n][d128]
#define PS 68      // sPt stride [col128][row64]

#define NITER      (SKV / BN)                    // 16
#define TOTAL_WORDS ((Bz * (SQ / BM)) * NITER * NT)   // 4,194,304

typedef unsigned long long u64;
typedef unsigned int u32;

// 32 MB static: K pre-transposed to [B][D][SKV]
__device__ float g_kt[(size_t)Bz * Dd * SKV];
// 16 MB static: dropout keep-words in attn read order:
//   word[((b*32+qt)*16 + iter)*256 + tid], bit (i*4+j) = keep(row 8tm+i, col 4tn+j)
__device__ u32 g_mask[TOTAL_WORDS];

// ---------------- f32x2 packed helpers ----------------
__device__ __forceinline__ u64 ffma2(u64 a, u64 b, u64 c) {
    u64 d; asm("fma.rn.f32x2 %0, %1, %2, %3;" : "=l"(d) : "l"(a), "l"(b), "l"(c));
    return d;
}
__device__ __forceinline__ u64 fmul2(u64 a, u64 b) {
    u64 d; asm("mul.rn.f32x2 %0, %1, %2;" : "=l"(d) : "l"(a), "l"(b));
    return d;
}
__device__ __forceinline__ u64 pk2(float lo, float hi) {
    u64 d; asm("mov.b64 %0, {%1, %2};" : "=l"(d)
               : "r"(__float_as_uint(lo)), "r"(__float_as_uint(hi)));
    return d;
}
__device__ __forceinline__ void upk2(u64 v, float& lo, float& hi) {
    u32 a, b; asm("mov.b64 {%0, %1}, %2;" : "=r"(a), "=r"(b) : "l"(v));
    lo = __uint_as_float(a); hi = __uint_as_float(b);
}

// ---------------- cp.async helpers ----------------
__device__ __forceinline__ void cpa16(u32 dst, const float* src) {
    asm volatile("cp.async.cg.shared.global [%0], [%1], 16;" :: "r"(dst), "l"(src));
}
#define CP_COMMIT() asm volatile("cp.async.commit_group;" ::: "memory")
#define CP_WAIT0()  asm volatile("cp.async.wait_group 0;" ::: "memory")
#define CP_WAIT1()  asm volatile("cp.async.wait_group 1;" ::: "memory")

// ---------------- Threefry-2x32-20, key=(0,42) ----------------
__device__ __forceinline__ void threefry_0_42(u32 x0, u32 x1, u32& y0, u32& y1) {
    const u32 ks1 = 42u;
    const u32 ks2 = 0x1BD11BDAu ^ 42u;
    x1 += ks1;
#define TF_R(r) { x0 += x1; x1 = __funnelshift_l(x1, x1, (r)); x1 ^= x0; }
    TF_R(13) TF_R(15) TF_R(26) TF_R(6)
    x0 += ks1; x1 += ks2 + 1u;
    TF_R(17) TF_R(29) TF_R(16) TF_R(24)
    x0 += ks2; x1 += 2u;
    TF_R(13) TF_R(15) TF_R(26) TF_R(6)
    x0 += 0u;  x1 += ks1 + 3u;
    TF_R(17) TF_R(29) TF_R(16) TF_R(24)
    x0 += ks1; x1 += ks2 + 4u;
    TF_R(13) TF_R(15) TF_R(26) TF_R(6)
    x0 += ks2; x1 += 5u;
#undef TF_R
    y0 = x0; y1 = x1;
}
// keep <=> fp32-uniform(bits) < 0.7  <=>  bits < (5872026 << 9)   (exact)
#define KEEP_THRESH 3006477312u

// ---------------------------------------------------------------------------
// Mask precompute: one thread -> one keep-word, laid out in attn read order.
// ---------------------------------------------------------------------------
__global__ __launch_bounds__(256, 6) void dropout_mask_kernel() {
    u32 w   = blockIdx.x * 256u + threadIdx.x;      // [0, TOTAL_WORDS)
    u32 ta  = w & 255u;                             // attn tid
    u32 it  = (w >> 8) & (NITER - 1);               // attn kv iter
    u32 cta = w >> 12;                              // b*32 + qtile
    u32 b   = cta >> 5;
    u32 qt  = cta & 31u;
    u32 tmc = ta >> 5, tnc = ta & 31u;

    u32 eb = (b * (u32)SQ + qt * (u32)BM + (tmc << 3)) * (u32)SKV
           + it * (u32)BN + (tnc << 2);
    u32 word = 0;
#pragma unroll
    for (int i = 0; i < 8; ++i) {
        u32 eRow = eb + ((u32)i << 11);
#pragma unroll
        for (int j = 0; j < 4; ++j) {
            u32 y0, y1;
            threefry_0_42(0u, eRow + (u32)j, y0, y1);
            word |= (u32)((y0 ^ y1) < KEEP_THRESH) << (i * 4 + j);
        }
    }
    g_mask[w] = word;
}

// ---------------------------------------------------------------------------
// K transpose: g_kt[b][d][s] = k[b][s][d]
// ---------------------------------------------------------------------------
__global__ __launch_bounds__(256, 4) void transpose_k_kernel(const float* __restrict__ k) {
    __shared__ float t[32][33];
    int b  = blockIdx.z;
    int s0 = blockIdx.x << 5;
    int d0 = blockIdx.y << 5;
    const float* kb = k + ((size_t)b * SKV + s0) * Dd + d0;
#pragma unroll
    for (int r = threadIdx.y; r < 32; r += 8)
        t[r][threadIdx.x] = kb[r * Dd + threadIdx.x];
    __syncthreads();
    float* kt = g_kt + ((size_t)b * Dd + d0) * SKV + s0;
#pragma unroll
    for (int r = threadIdx.y; r < 32; r += 8)
        kt[r * SKV + threadIdx.x] = t[threadIdx.x][r];
}

// ---------------------------------------------------------------------------
// Flash attention, fp32 FFMA2, cp.async K/V pipeline, precomputed mask words.
// CTA = (batch b, 64 q rows). 256 threads: tm = tid>>5 (0..7), tn = tid&31.
// Thread: S rows 8tm+i (i<8), S cols 4tn+j (j<4); O cols 4tn+j.
// l kept lane-local (deferred reduction at epilogue).
// ---------------------------------------------------------------------------
__global__ __launch_bounds__(NT, 1) void attn_kernel(
    const float* __restrict__ q, const float* __restrict__ v,
    const float* __restrict__ sf, float* __restrict__ out) {

    extern __shared__ float sm[];
    float* sQt = sm;                    // [128][QS]
    float* sKt = sQt + Dd * QS;         // [128][KS]  d-major, from g_kt
    float* sV  = sKt + Dd * KS;         // [128][VS]
    float* sPt = sV + BN * VS;          // [128][PS]  P^T masked

    const int tid = threadIdx.x;
    const int tm  = tid >> 5;           // 0..7
    const int tn  = tid & 31;           // 0..31
    const int b   = blockIdx.y;
    const int q0  = blockIdx.x * BM;
    const float scale = sf[b];

    const float* ktb = g_kt + (size_t)b * Dd * SKV;     // [d][s]
    const float* vb  = v + (size_t)b * SKV * Dd;        // [s][d]
    const u32* mkb = g_mask + ((size_t)(b * (SQ / BM) + blockIdx.x) * NITER) * NT + tid;

    // ---- prologue: start K(0) copy ----
    {
        u32 dK = (u32)__cvta_generic_to_shared(sKt);
#pragma unroll
        for (int it = 0; it < 16; ++it) {
            int id = it * NT + tid;             // 0..4095
            int d  = id >> 5;                   // 0..127
            int c  = (id & 31) << 2;            // float offset
            cpa16(dK + (u32)(d * KS + c) * 4u, ktb + (size_t)d * SKV + 0 + c);
        }
        CP_COMMIT();
    }

    // ---- stage Q (once), transposed + pre-scaled ----
    {
        const float* qb = q + ((size_t)b * SQ + q0) * Dd;
#pragma unroll
        for (int it = 0; it < 32; ++it) {
            int idx = it * NT + tid;            // 0..8191
            int r = idx >> 7;                   // 0..63
            int d = idx & 127;
            sQt[d * QS + r] = qb[idx] * scale;
        }
    }

    u64 acc[4][4];
    float m_i[8], l_i[8];                       // l_i: lane-local partial
#pragma unroll
    for (int ip = 0; ip < 4; ++ip)
#pragma unroll
        for (int j = 0; j < 4; ++j) acc[ip][j] = 0ull;
#pragma unroll
    for (int i = 0; i < 8; ++i) { m_i[i] = -INFINITY; l_i[i] = 0.f; }

    u32 dV = (u32)__cvta_generic_to_shared(sV);
    u32 dK = (u32)__cvta_generic_to_shared(sKt);

    for (int kv0 = 0; kv0 < SKV; kv0 += BN) {
        const int itn = kv0 / BN;
        // K(i) landed (only it may be pending at this point)
        CP_WAIT0();
        __syncthreads();        // K visible to all; prev PV done -> sV free

        // precomputed keep-word for this tile (needed ~10K cyc later)
        u32 mbits = __ldg(mkb + (size_t)itn * NT);

        // issue V(i); waited before PV (hidden by QK)
        {
#pragma unroll
            for (int it = 0; it < 16; ++it) {
                int id = it * NT + tid;
                int r  = id >> 5;
                int c  = (id & 31) << 2;
                cpa16(dV + (u32)(r * VS + c) * 4u,
                      vb + (size_t)(kv0 + r) * Dd + c);
            }
            CP_COMMIT();
        }

        // ---- S = Q@K^T via FFMA2 ----
        u64 s2[4][4];
#pragma unroll
        for (int ip = 0; ip < 4; ++ip)
#pragma unroll
            for (int j = 0; j < 4; ++j) s2[ip][j] = 0ull;

#pragma unroll 4
        for (int d = 0; d < Dd; ++d) {
            ulonglong2 qv = *(const ulonglong2*)(sQt + d * QS + (tm << 3));
            ulonglong2 qw = *(const ulonglong2*)(sQt + d * QS + (tm << 3) + 4);
            u64 q01 = qv.x, q23 = qv.y, q45 = qw.x, q67 = qw.y;
            float4 kf = *(const float4*)(sKt + d * KS + (tn << 2));
            u64 k0 = pk2(kf.x, kf.x), k1 = pk2(kf.y, kf.y);
            u64 k2 = pk2(kf.z, kf.z), k3 = pk2(kf.w, kf.w);
            s2[0][0] = ffma2(q01, k0, s2[0][0]);
            s2[0][1] = ffma2(q01, k1, s2[0][1]);
            s2[0][2] = ffma2(q01, k2, s2[0][2]);
            s2[0][3] = ffma2(q01, k3, s2[0][3]);
            s2[1][0] = ffma2(q23, k0, s2[1][0]);
            s2[1][1] = ffma2(q23, k1, s2[1][1]);
            s2[1][2] = ffma2(q23, k2, s2[1][2]);
            s2[1][3] = ffma2(q23, k3, s2[1][3]);
            s2[2][0] = ffma2(q45, k0, s2[2][0]);
            s2[2][1] = ffma2(q45, k1, s2[2][1]);
            s2[2][2] = ffma2(q45, k2, s2[2][2]);
            s2[2][3] = ffma2(q45, k3, s2[2][3]);
            s2[3][0] = ffma2(q67, k0, s2[3][0]);
            s2[3][1] = ffma2(q67, k1, s2[3][1]);
            s2[3][2] = ffma2(q67, k2, s2[3][2]);
            s2[3][3] = ffma2(q67, k3, s2[3][3]);
        }

        // ---- online softmax (m reduced per-iter; l lane-local) ----
        float p[8][4];
#pragma unroll
        for (int ip = 0; ip < 4; ++ip)
#pragma unroll
            for (int j = 0; j < 4; ++j)
                upk2(s2[ip][j], p[2 * ip][j], p[2 * ip + 1][j]);

        float fac[8];
#pragma unroll
        for (int i = 0; i < 8; ++i) {
            float mx = fmaxf(fmaxf(p[i][0], p[i][1]), fmaxf(p[i][2], p[i][3]));
#pragma unroll
            for (int off = 16; off >= 1; off >>= 1)
                mx = fmaxf(mx, __shfl_xor_sync(0xffffffffu, mx, off));
            float mnew = fmaxf(m_i[i], mx);
            fac[i] = __expf(m_i[i] - mnew);
            m_i[i] = mnew;
            float rs = 0.f;
#pragma unroll
            for (int j = 0; j < 4; ++j) {
                p[i][j] = __expf(p[i][j] - mnew);
                rs += p[i][j];
            }
            l_i[i] = l_i[i] * fac[i] + rs;      // lane-local partial
        }
#pragma unroll
        for (int ip = 0; ip < 4; ++ip) {
            u64 f2 = pk2(fac[2 * ip], fac[2 * ip + 1]);
#pragma unroll
            for (int j = 0; j < 4; ++j) acc[ip][j] = fmul2(acc[ip][j], f2);
        }

        // ---- write masked P^T (apply keep bits) ----
#pragma unroll
        for (int j = 0; j < 4; ++j) {
            int c = (tn << 2) + j;
            float4 w0, w1;
            w0.x = (mbits >> (0 + j)) & 1u  ? p[0][j] : 0.f;
            w0.y = (mbits >> (4 + j)) & 1u  ? p[1][j] : 0.f;
            w0.z = (mbits >> (8 + j)) & 1u  ? p[2][j] : 0.f;
            w0.w = (mbits >> (12 + j)) & 1u ? p[3][j] : 0.f;
            w1.x = (mbits >> (16 + j)) & 1u ? p[4][j] : 0.f;
            w1.y = (mbits >> (20 + j)) & 1u ? p[5][j] : 0.f;
            w1.z = (mbits >> (24 + j)) & 1u ? p[6][j] : 0.f;
            w1.w = (mbits >> (28 + j)) & 1u ? p[7][j] : 0.f;
            *(float4*)(sPt + c * PS + (tm << 3)) = w0;
            *(float4*)(sPt + c * PS + (tm << 3) + 4) = w1;
        }
        __syncthreads();        // all QK reads of sKt done; P visible

        // issue K(i+1) into sKt (hidden by PV)
        if (kv0 + BN < SKV) {
#pragma unroll
            for (int it = 0; it < 16; ++it) {
                int id = it * NT + tid;
                int d  = id >> 5;
                int c  = (id & 31) << 2;
                cpa16(dK + (u32)(d * KS + c) * 4u,
                      ktb + (size_t)d * SKV + (kv0 + BN) + c);
            }
            CP_COMMIT();
            CP_WAIT1();         // V(i) done; K(i+1) may fly
        } else {
            CP_WAIT0();         // V(i) done
        }
        __syncthreads();        // V visible to all

        // ---- acc += P^T' @ V via FFMA2 ----
#pragma unroll 4
        for (int n = 0; n < BN; ++n) {
            ulonglong2 pA = *(const ulonglong2*)(sPt + n * PS + (tm << 3));
            ulonglong2 pB = *(const ulonglong2*)(sPt + n * PS + (tm << 3) + 4);
            u64 p01 = pA.x, p23 = pA.y, p45 = pB.x, p67 = pB.y;
            float4 vf = *(const float4*)(sV + n * VS + (tn << 2));
            u64 v0 = pk2(vf.x, vf.x), v1 = pk2(vf.y, vf.y);
            u64 v2 = pk2(vf.z, vf.z), v3 = pk2(vf.w, vf.w);
            acc[0][0] = ffma2(p01, v0, acc[0][0]);
            acc[0][1] = ffma2(p01, v1, acc[0][1]);
            acc[0][2] = ffma2(p01, v2, acc[0][2]);
            acc[0][3] = ffma2(p01, v3, acc[0][3]);
            acc[1][0] = ffma2(p23, v0, acc[1][0]);
            acc[1][1] = ffma2(p23, v1, acc[1][1]);
            acc[1][2] = ffma2(p23, v2, acc[1][2]);
            acc[1][3] = ffma2(p23, v3, acc[1][3]);
            acc[2][0] = ffma2(p45, v0, acc[2][0]);
            acc[2][1] = ffma2(p45, v1, acc[2][1]);
            acc[2][2] = ffma2(p45, v2, acc[2][2]);
            acc[3][0] = ffma2(p67, v0, acc[3][0]);
            acc[2][3] = ffma2(p45, v3, acc[2][3]);
            acc[3][1] = ffma2(p67, v1, acc[3][1]);
            acc[3][2] = ffma2(p67, v2, acc[3][2]);
            acc[3][3] = ffma2(p67, v3, acc[3][3]);
        }
    }

    // ---- epilogue: reduce l across lanes, out = acc / (l * 0.7) ----
    float lr[8];
#pragma unroll
    for (int i = 0; i < 8; ++i) {
        float s = l_i[i];
#pragma unroll
        for (int off = 16; off >= 1; off >>= 1)
            s += __shfl_xor_sync(0xffffffffu, s, off);
        lr[i] = s;
    }
#pragma unroll
    for (int ip = 0; ip < 4; ++ip) {
        float inv0 = 1.0f / (lr[2 * ip] * 0.7f);
        float inv1 = 1.0f / (lr[2 * ip + 1] * 0.7f);
        float lo[4], hi[4];
#pragma unroll
        for (int j = 0; j < 4; ++j) upk2(acc[ip][j], lo[j], hi[j]);
        int r0 = q0 + (tm << 3) + 2 * ip;
        float* o0 = out + ((size_t)b * SQ + r0) * Dd + (tn << 2);
        float* o1 = o0 + Dd;
        *(float4*)o0 = make_float4(lo[0] * inv0, lo[1] * inv0, lo[2] * inv0, lo[3] * inv0);
        *(float4*)o1 = make_float4(hi[0] * inv1, hi[1] * inv1, hi[2] * inv1, hi[3] * inv1);
    }
}

// ---------------------------------------------------------------------------
extern "C" void kernel_launch(void* const* d_in, const int* in_sizes, int n_in,
                              void* d_out, int out_size) {
    const float* q  = (const float*)d_in[0];
    const float* k  = (const float*)d_in[1];
    const float* v  = (const float*)d_in[2];
    const float* sf = (const float*)d_in[3];
    float* out = (float*)d_out;

    // 1) dropout keep-words (attn read order)
    dropout_mask_kernel<<<TOTAL_WORDS / 256, 256>>>();

    // 2) K -> g_kt transpose  [B][D][SKV]
    {
        dim3 grid(SKV / 32, Dd / 32, Bz);
        transpose_k_kernel<<<grid, dim3(32, 8)>>>(k);
    }

    // 3) Flash attention
    size_t smem_bytes = (size_t)(Dd * QS + Dd * KS + BN * VS + BN * PS) * 4;
    cudaFuncSetAttribute(attn_kernel, cudaFuncAttributeMaxDynamicSharedMemorySize,
                         (int)smem_bytes);
    dim3 grid(SQ / BM, Bz);
    attn_kernel<<<grid, NT, smem_bytes>>>(q, v, sf, out);
}

// round 14
// speedup vs baseline: 1.1796x; 1.0034x over previous
#include <cuda_runtime.h>
#include <cstdint>
#include <math.h>

#define Bz   32
#define SQ   2048
#define SKV  2048
#define Dd   128
#define BM   64
#define BN   128
#define NT   256

#define QS 68      // sQt stride [d][row64]
#define KS 132     // sKt stride [d][kv128]
#define VS 132     // sV  stride [n][d128]
#define PS 68      // sPt stride [col128][row64]

#define NITER      (SKV / BN)                    // 16
#define TOTAL_WORDS ((Bz * (SQ / BM)) * NITER * NT)   // 4,194,304
#define MASK_BLOCKS (TOTAL_WORDS / 256)          // 16384
#define TPOSE_BLOCKS (Bz * (Dd / 32) * (SKV / 32))    // 8192

typedef unsigned long long u64;
typedef unsigned int u32;

// 32 MB static: K pre-transposed to [B][D][SKV]
__device__ float g_kt[(size_t)Bz * Dd * SKV];
// 16 MB static: dropout keep-words in attn read order:
//   word[((b*32+qt)*16 + iter)*256 + tid], bit (i*4+j) = keep(row 8tm+i, col 4tn+j)
__device__ u32 g_mask[TOTAL_WORDS];

// ---------------- f32x2 packed helpers ----------------
__device__ __forceinline__ u64 ffma2(u64 a, u64 b, u64 c) {
    u64 d; asm("fma.rn.f32x2 %0, %1, %2, %3;" : "=l"(d) : "l"(a), "l"(b), "l"(c));
    return d;
}
__device__ __forceinline__ u64 fmul2(u64 a, u64 b) {
    u64 d; asm("mul.rn.f32x2 %0, %1, %2;" : "=l"(d) : "l"(a), "l"(b));
    return d;
}
__device__ __forceinline__ u64 pk2(float lo, float hi) {
    u64 d; asm("mov.b64 %0, {%1, %2};" : "=l"(d)
               : "r"(__float_as_uint(lo)), "r"(__float_as_uint(hi)));
    return d;
}
__device__ __forceinline__ void upk2(u64 v, float& lo, float& hi) {
    u32 a, b; asm("mov.b64 {%0, %1}, %2;" : "=r"(a), "=r"(b) : "l"(v));
    lo = __uint_as_float(a); hi = __uint_as_float(b);
}

// ---------------- cp.async helpers ----------------
__device__ __forceinline__ void cpa16(u32 dst, const float* src) {
    asm volatile("cp.async.cg.shared.global [%0], [%1], 16;" :: "r"(dst), "l"(src));
}
#define CP_COMMIT() asm volatile("cp.async.commit_group;" ::: "memory")
#define CP_WAIT0()  asm volatile("cp.async.wait_group 0;" ::: "memory")
#define CP_WAIT1()  asm volatile("cp.async.wait_group 1;" ::: "memory")

// ---------------- Threefry-2x32-20, key=(0,42) ----------------
// `one` is a runtime 1 (blockDim.y): forces the adds onto the fma pipe
// (IMAD.LO) so SHF/LOP3 (alu pipe) and adds (fma pipe) run in parallel.
__device__ __forceinline__ void threefry_0_42_bal(u32 x0, u32 x1, u32 one,
                                                  u32& y0, u32& y1) {
    const u32 ks1 = 42u;
    const u32 ks2 = 0x1BD11BDAu ^ 42u;
    x1 = x1 * one + ks1;
#define TF_R(r) { x0 = x0 * one + x1; x1 = __funnelshift_l(x1, x1, (r)); x1 ^= x0; }
    TF_R(13) TF_R(15) TF_R(26) TF_R(6)
    x0 = x0 * one + ks1; x1 = x1 * one + (ks2 + 1u);
    TF_R(17) TF_R(29) TF_R(16) TF_R(24)
    x0 = x0 * one + ks2; x1 = x1 * one + 2u;
    TF_R(13) TF_R(15) TF_R(26) TF_R(6)
    x1 = x1 * one + (ks1 + 3u);
    TF_R(17) TF_R(29) TF_R(16) TF_R(24)
    x0 = x0 * one + ks1; x1 = x1 * one + (ks2 + 4u);
    TF_R(13) TF_R(15) TF_R(26) TF_R(6)
    x0 = x0 * one + ks2; x1 = x1 * one + 5u;
#undef TF_R
    y0 = x0; y1 = x1;
}
// keep <=> fp32-uniform(bits) < 0.7  <=>  bits < (5872026 << 9)   (exact)
#define KEEP_THRESH 3006477312u

// ---------------------------------------------------------------------------
// Fused prep kernel: blocks [0, MASK_BLOCKS) compute dropout keep-words
// (alu/fma-bound); blocks [MASK_BLOCKS, +TPOSE_BLOCKS) transpose K into g_kt
// (DRAM-bound). The two populations overlap on-chip.
// ---------------------------------------------------------------------------
__global__ __launch_bounds__(256, 6) void prep_kernel(const float* __restrict__ k) {
    if (blockIdx.x < MASK_BLOCKS) {
        const u32 one = blockDim.y;                 // runtime 1
        u32 w   = blockIdx.x * 256u + threadIdx.x;  // [0, TOTAL_WORDS)
        u32 ta  = w & 255u;                         // attn tid
        u32 it  = (w >> 8) & (NITER - 1);           // attn kv iter
        u32 cta = w >> 12;                          // b*32 + qtile
        u32 b   = cta >> 5;
        u32 qt  = cta & 31u;
        u32 tmc = ta >> 5, tnc = ta & 31u;

        u32 eb = (b * (u32)SQ + qt * (u32)BM + (tmc << 3)) * (u32)SKV
               + it * (u32)BN + (tnc << 2);
        u32 word = 0;
#pragma unroll
        for (int i = 0; i < 8; ++i) {
            u32 eRow = eb + ((u32)i << 11);
#pragma unroll
            for (int j = 0; j < 4; ++j) {
                u32 y0, y1;
                threefry_0_42_bal(0u, eRow + (u32)j, one, y0, y1);
                word |= (u32)((y0 ^ y1) < KEEP_THRESH) << (i * 4 + j);
            }
        }
        g_mask[w] = word;
    } else {
        // ---- K transpose: g_kt[b][d][s] = k[b][s][d] ----
        __shared__ float t[32][33];
        u32 bid = blockIdx.x - MASK_BLOCKS;         // [0, 8192)
        int b  = bid >> 8;                          // 32 b's, 256 tiles each
        int d0 = ((bid >> 6) & 3) << 5;             // 4 d-tiles
        int s0 = (bid & 63) << 5;                   // 64 s-tiles
        int tx = threadIdx.x & 31;
        int ty = threadIdx.x >> 5;                  // 0..7
        const float* kb = k + ((size_t)b * SKV + s0) * Dd + d0;
#pragma unroll
        for (int r = ty; r < 32; r += 8)
            t[r][tx] = kb[r * Dd + tx];
        __syncthreads();
        float* kt = g_kt + ((size_t)b * Dd + d0) * SKV + s0;
#pragma unroll
        for (int r = ty; r < 32; r += 8)
            kt[r * SKV + tx] = t[tx][r];
    }
}

// ---------------------------------------------------------------------------
// Flash attention, fp32 FFMA2, cp.async K/V pipeline, precomputed mask words.
// CTA = (batch b, 64 q rows). 256 threads: tm = tid>>5 (0..7), tn = tid&31.
// Thread: S rows 8tm+i (i<8), S cols 4tn+j (j<4); O cols 4tn+j.
// l kept lane-local (deferred reduction at epilogue).
// ---------------------------------------------------------------------------
__global__ __launch_bounds__(NT, 1) void attn_kernel(
    const float* __restrict__ q, const float* __restrict__ v,
    const float* __restrict__ sf, float* __restrict__ out) {

    extern __shared__ float sm[];
    float* sQt = sm;                    // [128][QS]
    float* sKt = sQt + Dd * QS;         // [128][KS]  d-major, from g_kt
    float* sV  = sKt + Dd * KS;         // [128][VS]
    float* sPt = sV + BN * VS;          // [128][PS]  P^T masked

    const int tid = threadIdx.x;
    const int tm  = tid >> 5;           // 0..7
    const int tn  = tid & 31;           // 0..31
    const int b   = blockIdx.y;
    const int q0  = blockIdx.x * BM;
    const float scale = sf[b];

    const float* ktb = g_kt + (size_t)b * Dd * SKV;     // [d][s]
    const float* vb  = v + (size_t)b * SKV * Dd;        // [s][d]
    const u32* mkb = g_mask + ((size_t)(b * (SQ / BM) + blockIdx.x) * NITER) * NT + tid;

    // ---- prologue: start K(0) copy ----
    {
        u32 dK = (u32)__cvta_generic_to_shared(sKt);
#pragma unroll
        for (int it = 0; it < 16; ++it) {
            int id = it * NT + tid;             // 0..4095
            int d  = id >> 5;                   // 0..127
            int c  = (id & 31) << 2;            // float offset
            cpa16(dK + (u32)(d * KS + c) * 4u, ktb + (size_t)d * SKV + 0 + c);
        }
        CP_COMMIT();
    }

    // ---- stage Q (once), transposed + pre-scaled ----
    {
        const float* qb = q + ((size_t)b * SQ + q0) * Dd;
#pragma unroll
        for (int it = 0; it < 32; ++it) {
            int idx = it * NT + tid;            // 0..8191
            int r = idx >> 7;                   // 0..63
            int d = idx & 127;
            sQt[d * QS + r] = qb[idx] * scale;
        }
    }

    u64 acc[4][4];
    float m_i[8], l_i[8];                       // l_i: lane-local partial
#pragma unroll
    for (int ip = 0; ip < 4; ++ip)
#pragma unroll
        for (int j = 0; j < 4; ++j) acc[ip][j] = 0ull;
#pragma unroll
    for (int i = 0; i < 8; ++i) { m_i[i] = -INFINITY; l_i[i] = 0.f; }

    u32 dV = (u32)__cvta_generic_to_shared(sV);
    u32 dK = (u32)__cvta_generic_to_shared(sKt);

    for (int kv0 = 0; kv0 < SKV; kv0 += BN) {
        const int itn = kv0 / BN;
        // K(i) landed (only it may be pending at this point)
        CP_WAIT0();
        __syncthreads();        // K visible to all; prev PV done -> sV free

        // precomputed keep-word for this tile (needed ~10K cyc later)
        u32 mbits = __ldg(mkb + (size_t)itn * NT);

        // issue V(i); waited before PV (hidden by QK)
        {
#pragma unroll
            for (int it = 0; it < 16; ++it) {
                int id = it * NT + tid;
                int r  = id >> 5;
                int c  = (id & 31) << 2;
                cpa16(dV + (u32)(r * VS + c) * 4u,
                      vb + (size_t)(kv0 + r) * Dd + c);
            }
            CP_COMMIT();
        }

        // ---- S = Q@K^T via FFMA2 ----
        u64 s2[4][4];
#pragma unroll
        for (int ip = 0; ip < 4; ++ip)
#pragma unroll
            for (int j = 0; j < 4; ++j) s2[ip][j] = 0ull;

#pragma unroll 4
        for (int d = 0; d < Dd; ++d) {
            ulonglong2 qv = *(const ulonglong2*)(sQt + d * QS + (tm << 3));
            ulonglong2 qw = *(const ulonglong2*)(sQt + d * QS + (tm << 3) + 4);
            u64 q01 = qv.x, q23 = qv.y, q45 = qw.x, q67 = qw.y;
            float4 kf = *(const float4*)(sKt + d * KS + (tn << 2));
            u64 k0 = pk2(kf.x, kf.x), k1 = pk2(kf.y, kf.y);
            u64 k2 = pk2(kf.z, kf.z), k3 = pk2(kf.w, kf.w);
            s2[0][0] = ffma2(q01, k0, s2[0][0]);
            s2[0][1] = ffma2(q01, k1, s2[0][1]);
            s2[0][2] = ffma2(q01, k2, s2[0][2]);
            s2[0][3] = ffma2(q01, k3, s2[0][3]);
            s2[1][0] = ffma2(q23, k0, s2[1][0]);
            s2[1][1] = ffma2(q23, k1, s2[1][1]);
            s2[1][2] = ffma2(q23, k2, s2[1][2]);
            s2[1][3] = ffma2(q23, k3, s2[1][3]);
            s2[2][0] = ffma2(q45, k0, s2[2][0]);
            s2[2][1] = ffma2(q45, k1, s2[2][1]);
            s2[2][2] = ffma2(q45, k2, s2[2][2]);
            s2[2][3] = ffma2(q45, k3, s2[2][3]);
            s2[3][0] = ffma2(q67, k0, s2[3][0]);
            s2[3][1] = ffma2(q67, k1, s2[3][1]);
            s2[3][2] = ffma2(q67, k2, s2[3][2]);
            s2[3][3] = ffma2(q67, k3, s2[3][3]);
        }

        // ---- online softmax (m reduced per-iter; l lane-local) ----
        float p[8][4];
#pragma unroll
        for (int ip = 0; ip < 4; ++ip)
#pragma unroll
            for (int j = 0; j < 4; ++j)
                upk2(s2[ip][j], p[2 * ip][j], p[2 * ip + 1][j]);

        float fac[8];
#pragma unroll
        for (int i = 0; i < 8; ++i) {
            float mx = fmaxf(fmaxf(p[i][0], p[i][1]), fmaxf(p[i][2], p[i][3]));
#pragma unroll
            for (int off = 16; off >= 1; off >>= 1)
                mx = fmaxf(mx, __shfl_xor_sync(0xffffffffu, mx, off));
            float mnew = fmaxf(m_i[i], mx);
            fac[i] = __expf(m_i[i] - mnew);
            m_i[i] = mnew;
            float rs = 0.f;
#pragma unroll
            for (int j = 0; j < 4; ++j) {
                p[i][j] = __expf(p[i][j] - mnew);
                rs += p[i][j];
            }
            l_i[i] = l_i[i] * fac[i] + rs;      // lane-local partial
        }
#pragma unroll
        for (int ip = 0; ip < 4; ++ip) {
            u64 f2 = pk2(fac[2 * ip], fac[2 * ip + 1]);
#pragma unroll
            for (int j = 0; j < 4; ++j) acc[ip][j] = fmul2(acc[ip][j], f2);
        }

        // ---- write masked P^T (apply keep bits) ----
#pragma unroll
        for (int j = 0; j < 4; ++j) {
            int c = (tn << 2) + j;
            float4 w0, w1;
            w0.x = (mbits >> (0 + j)) & 1u  ? p[0][j] : 0.f;
            w0.y = (mbits >> (4 + j)) & 1u  ? p[1][j] : 0.f;
            w0.z = (mbits >> (8 + j)) & 1u  ? p[2][j] : 0.f;
            w0.w = (mbits >> (12 + j)) & 1u ? p[3][j] : 0.f;
            w1.x = (mbits >> (16 + j)) & 1u ? p[4][j] : 0.f;
            w1.y = (mbits >> (20 + j)) & 1u ? p[5][j] : 0.f;
            w1.z = (mbits >> (24 + j)) & 1u ? p[6][j] : 0.f;
            w1.w = (mbits >> (28 + j)) & 1u ? p[7][j] : 0.f;
            *(float4*)(sPt + c * PS + (tm << 3)) = w0;
            *(float4*)(sPt + c * PS + (tm << 3) + 4) = w1;
        }
        __syncthreads();        // all QK reads of sKt done; P visible

        // issue K(i+1) into sKt (hidden by PV)
        if (kv0 + BN < SKV) {
#pragma unroll
            for (int it = 0; it < 16; ++it) {
                int id = it * NT + tid;
                int d  = id >> 5;
                int c  = (id & 31) << 2;
                cpa16(dK + (u32)(d * KS + c) * 4u,
                      ktb + (size_t)d * SKV + (kv0 + BN) + c);
            }
            CP_COMMIT();
            CP_WAIT1();         // V(i) done; K(i+1) may fly
        } else {
            CP_WAIT0();         // V(i) done
        }
        __syncthreads();        // V visible to all

        // ---- acc += P^T' @ V via FFMA2 ----
#pragma unroll 4
        for (int n = 0; n < BN; ++n) {
            ulonglong2 pA = *(const ulonglong2*)(sPt + n * PS + (tm << 3));
            ulonglong2 pB = *(const ulonglong2*)(sPt + n * PS + (tm << 3) + 4);
            u64 p01 = pA.x, p23 = pA.y, p45 = pB.x, p67 = pB.y;
            float4 vf = *(const float4*)(sV + n * VS + (tn << 2));
            u64 v0 = pk2(vf.x, vf.x), v1 = pk2(vf.y, vf.y);
            u64 v2 = pk2(vf.z, vf.z), v3 = pk2(vf.w, vf.w);
            acc[0][0] = ffma2(p01, v0, acc[0][0]);
            acc[0][1] = ffma2(p01, v1, acc[0][1]);
            acc[0][2] = ffma2(p01, v2, acc[0][2]);
            acc[0][3] = ffma2(p01, v3, acc[0][3]);
            acc[1][0] = ffma2(p23, v0, acc[1][0]);
            acc[1][1] = ffma2(p23, v1, acc[1][1]);
            acc[1][2] = ffma2(p23, v2, acc[1][2]);
            acc[1][3] = ffma2(p23, v3, acc[1][3]);
            acc[2][0] = ffma2(p45, v0, acc[2][0]);
            acc[2][1] = ffma2(p45, v1, acc[2][1]);
            acc[2][2] = ffma2(p45, v2, acc[2][2]);
            acc[3][0] = ffma2(p67, v0, acc[3][0]);
            acc[2][3] = ffma2(p45, v3, acc[2][3]);
            acc[3][1] = ffma2(p67, v1, acc[3][1]);
            acc[3][2] = ffma2(p67, v2, acc[3][2]);
            acc[3][3] = ffma2(p67, v3, acc[3][3]);
        }
    }

    // ---- epilogue: reduce l across lanes, out = acc / (l * 0.7) ----
    float lr[8];
#pragma unroll
    for (int i = 0; i < 8; ++i) {
        float s = l_i[i];
#pragma unroll
        for (int off = 16; off >= 1; off >>= 1)
            s += __shfl_xor_sync(0xffffffffu, s, off);
        lr[i] = s;
    }
#pragma unroll
    for (int ip = 0; ip < 4; ++ip) {
        float inv0 = 1.0f / (lr[2 * ip] * 0.7f);
        float inv1 = 1.0f / (lr[2 * ip + 1] * 0.7f);
        float lo[4], hi[4];
#pragma unroll
        for (int j = 0; j < 4; ++j) upk2(acc[ip][j], lo[j], hi[j]);
        int r0 = q0 + (tm << 3) + 2 * ip;
        float* o0 = out + ((size_t)b * SQ + r0) * Dd + (tn << 2);
        float* o1 = o0 + Dd;
        *(float4*)o0 = make_float4(lo[0] * inv0, lo[1] * inv0, lo[2] * inv0, lo[3] * inv0);
        *(float4*)o1 = make_float4(hi[0] * inv1, hi[1] * inv1, hi[2] * inv1, hi[3] * inv1);
    }
}

// ---------------------------------------------------------------------------
extern "C" void kernel_launch(void* const* d_in, const int* in_sizes, int n_in,
                              void* d_out, int out_size) {
    const float* q  = (const float*)d_in[0];
    const float* k  = (const float*)d_in[1];
    const float* v  = (const float*)d_in[2];
    const float* sf = (const float*)d_in[3];
    float* out = (float*)d_out;

    // 1) fused prep: dropout keep-words (alu/fma) + K transpose (DRAM), overlapped
    prep_kernel<<<MASK_BLOCKS + TPOSE_BLOCKS, dim3(256, 1, 1)>>>(k);

    // 2) Flash attention
    size_t smem_bytes = (size_t)(Dd * QS + Dd * KS + BN * VS + BN * PS) * 4;
    cudaFuncSetAttribute(attn_kernel, cudaFuncAttributeMaxDynamicSharedMemorySize,
                         (int)smem_bytes);
    dim3 grid(SQ / BM, Bz);
    attn_kernel<<<grid, NT, smem_bytes>>>(q, v, sf, out);
}

// round 16
// speedup vs baseline: 1.1889x; 1.0079x over previous
#include <cuda_runtime.h>
#include <cstdint>
#include <math.h>

#define Bz   32
#define SQ   2048
#define SKV  2048
#define Dd   128
#define BM   64
#define BN   128
#define NT   256

#define QS 68      // sQt stride [d][row64]
#define KS 132     // sKt stride [d][kv128]
#define VS 132     // sV  stride [n][d128]
#define PS 68      // sPt stride [col128][row64]

#define NITER      (SKV / BN)                    // 16
#define TOTAL_WORDS ((Bz * (SQ / BM)) * NITER * NT)   // 4,194,304
#define MASK_BLOCKS (TOTAL_WORDS / 256)          // 16384
#define TPOSE_BLOCKS (Bz * (Dd / 32) * (SKV / 32))    // 8192

typedef unsigned long long u64;
typedef unsigned int u32;

// 32 MB static: K pre-transposed to [B][D][SKV]
__device__ float g_kt[(size_t)Bz * Dd * SKV];
// 16 MB static: dropout keep-words in attn read order:
//   word[((b*32+qt)*16 + iter)*256 + tid], bit (i*4+j) = keep(row 8tm+i, col 4tn+j)
__device__ u32 g_mask[TOTAL_WORDS];

// ---------------- f32x2 packed helpers ----------------
__device__ __forceinline__ u64 ffma2(u64 a, u64 b, u64 c) {
    u64 d; asm("fma.rn.f32x2 %0, %1, %2, %3;" : "=l"(d) : "l"(a), "l"(b), "l"(c));
    return d;
}
__device__ __forceinline__ u64 fmul2(u64 a, u64 b) {
    u64 d; asm("mul.rn.f32x2 %0, %1, %2;" : "=l"(d) : "l"(a), "l"(b));
    return d;
}
__device__ __forceinline__ u64 pk2(float lo, float hi) {
    u64 d; asm("mov.b64 %0, {%1, %2};" : "=l"(d)
               : "r"(__float_as_uint(lo)), "r"(__float_as_uint(hi)));
    return d;
}
__device__ __forceinline__ void upk2(u64 v, float& lo, float& hi) {
    u32 a, b; asm("mov.b64 {%0, %1}, %2;" : "=r"(a), "=r"(b) : "l"(v));
    lo = __uint_as_float(a); hi = __uint_as_float(b);
}

// ---------------- cp.async helpers ----------------
__device__ __forceinline__ void cpa16(u32 dst, const float* src) {
    asm volatile("cp.async.cg.shared.global [%0], [%1], 16;" :: "r"(dst), "l"(src));
}
#define CP_COMMIT() asm volatile("cp.async.commit_group;" ::: "memory")
#define CP_WAIT0()  asm volatile("cp.async.wait_group 0;" ::: "memory")

// ---------------- Threefry-2x32-20, key=(0,42) ----------------
__device__ __forceinline__ void threefry_0_42(u32 x0, u32 x1, u32& y0, u32& y1) {
    const u32 ks1 = 42u;
    const u32 ks2 = 0x1BD11BDAu ^ 42u;
    x1 += ks1;
#define TF_R(r) { x0 += x1; x1 = __funnelshift_l(x1, x1, (r)); x1 ^= x0; }
    TF_R(13) TF_R(15) TF_R(26) TF_R(6)
    x0 += ks1; x1 += ks2 + 1u;
    TF_R(17) TF_R(29) TF_R(16) TF_R(24)
    x0 += ks2; x1 += 2u;
    TF_R(13) TF_R(15) TF_R(26) TF_R(6)
    x1 += ks1 + 3u;
    TF_R(17) TF_R(29) TF_R(16) TF_R(24)
    x0 += ks1; x1 += ks2 + 4u;
    TF_R(13) TF_R(15) TF_R(26) TF_R(6)
    x0 += ks2; x1 += 5u;
#undef TF_R
    y0 = x0; y1 = x1;
}
// keep <=> fp32-uniform(bits) < 0.7  <=>  bits < (5872026 << 9)   (exact)
#define KEEP_THRESH 3006477312u

// ---------------------------------------------------------------------------
// Fused prep kernel: blocks [0, MASK_BLOCKS) compute dropout keep-words
// (alu-bound); blocks [MASK_BLOCKS, +TPOSE_BLOCKS) transpose K into g_kt
// (DRAM-bound). The two populations overlap on-chip.
// ---------------------------------------------------------------------------
__global__ __launch_bounds__(256, 6) void prep_kernel(const float* __restrict__ k) {
    if (blockIdx.x < MASK_BLOCKS) {
        u32 w   = blockIdx.x * 256u + threadIdx.x;  // [0, TOTAL_WORDS)
        u32 ta  = w & 255u;                         // attn tid
        u32 it  = (w >> 8) & (NITER - 1);           // attn kv iter
        u32 cta = w >> 12;                          // b*32 + qtile
        u32 b   = cta >> 5;
        u32 qt  = cta & 31u;
        u32 tmc = ta >> 5, tnc = ta & 31u;

        u32 eb = (b * (u32)SQ + qt * (u32)BM + (tmc << 3)) * (u32)SKV
               + it * (u32)BN + (tnc << 2);
        u32 word = 0;
#pragma unroll
        for (int i = 0; i < 8; ++i) {
            u32 eRow = eb + ((u32)i << 11);
#pragma unroll
            for (int j = 0; j < 4; ++j) {
                u32 y0, y1;
                threefry_0_42(0u, eRow + (u32)j, y0, y1);
                word |= (u32)((y0 ^ y1) < KEEP_THRESH) << (i * 4 + j);
            }
        }
        g_mask[w] = word;
    } else {
        // ---- K transpose: g_kt[b][d][s] = k[b][s][d] ----
        __shared__ float t[32][33];
        u32 bid = blockIdx.x - MASK_BLOCKS;         // [0, 8192)
        int b  = bid >> 8;                          // 32 b's, 256 tiles each
        int d0 = ((bid >> 6) & 3) << 5;             // 4 d-tiles
        int s0 = (bid & 63) << 5;                   // 64 s-tiles
        int tx = threadIdx.x & 31;
        int ty = threadIdx.x >> 5;                  // 0..7
        const float* kb = k + ((size_t)b * SKV + s0) * Dd + d0;
#pragma unroll
        for (int r = ty; r < 32; r += 8)
            t[r][tx] = kb[r * Dd + tx];
        __syncthreads();
        float* kt = g_kt + ((size_t)b * Dd + d0) * SKV + s0;
#pragma unroll
        for (int r = ty; r < 32; r += 8)
            kt[r * SKV + tx] = t[tx][r];
    }
}

// ---------------------------------------------------------------------------
// Flash attention, fp32 FFMA2, cp.async K/V pipeline, precomputed mask words.
// 2 barriers/iter; explicit smem prefetch pipelining in both GEMMs.
// CTA = (batch b, 64 q rows). 256 threads: tm = tid>>5 (0..7), tn = tid&31.
// ---------------------------------------------------------------------------
__global__ __launch_bounds__(NT, 1) void attn_kernel(
    const float* __restrict__ q, const float* __restrict__ v,
    const float* __restrict__ sf, float* __restrict__ out) {

    extern __shared__ float sm[];
    float* sQt = sm;                    // [128][QS]
    float* sKt = sQt + Dd * QS;         // [128][KS]  d-major, from g_kt
    float* sV  = sKt + Dd * KS;         // [128][VS]
    float* sPt = sV + BN * VS;          // [128][PS]  P^T masked (+512B tail pad)

    const int tid = threadIdx.x;
    const int tm  = tid >> 5;           // 0..7
    const int tn  = tid & 31;           // 0..31
    const int b   = blockIdx.y;
    const int q0  = blockIdx.x * BM;
    const float scale = sf[b];

    const float* ktb = g_kt + (size_t)b * Dd * SKV;     // [d][s]
    const float* vb  = v + (size_t)b * SKV * Dd;        // [s][d]
    const u32* mkb = g_mask + ((size_t)(b * (SQ / BM) + blockIdx.x) * NITER) * NT + tid;

    u32 dV = (u32)__cvta_generic_to_shared(sV);
    u32 dK = (u32)__cvta_generic_to_shared(sKt);

    // ---- prologue: start K(0) copy ----
#pragma unroll
    for (int it = 0; it < 16; ++it) {
        int id = it * NT + tid;             // 0..4095
        int d  = id >> 5;                   // 0..127
        int c  = (id & 31) << 2;            // float offset
        cpa16(dK + (u32)(d * KS + c) * 4u, ktb + (size_t)d * SKV + 0 + c);
    }
    CP_COMMIT();

    // ---- stage Q (once), transposed + pre-scaled ----
    {
        const float* qb = q + ((size_t)b * SQ + q0) * Dd;
#pragma unroll
        for (int it = 0; it < 32; ++it) {
            int idx = it * NT + tid;            // 0..8191
            int r = idx >> 7;                   // 0..63
            int d = idx & 127;
            sQt[d * QS + r] = qb[idx] * scale;
        }
    }

    u64 acc[4][4];
    float m_i[8], l_i[8];                       // l_i: lane-local partial
#pragma unroll
    for (int ip = 0; ip < 4; ++ip)
#pragma unroll
        for (int j = 0; j < 4; ++j) acc[ip][j] = 0ull;
#pragma unroll
    for (int i = 0; i < 8; ++i) { m_i[i] = -INFINITY; l_i[i] = 0.f; }

    const float* kPtr = sKt + (tn << 2);
    const float* qPtr = sQt + (tm << 3);
    const float* pPtr = sPt + (tm << 3);
    const float* vPtr = sV + (tn << 2);

    for (int kv0 = 0; kv0 < SKV; kv0 += BN) {
        const int itn = kv0 / BN;
        // K(i) landed (the only pending group at this point)
        CP_WAIT0();
        __syncthreads();        // A: K(i)+Q visible; sV free (prev PV done)

        // precomputed keep-word for this tile (needed ~10K cyc later)
        u32 mbits = __ldg(mkb + (size_t)itn * NT);

        // issue V(i); waited before P-write (hidden under QK+softmax)
#pragma unroll
        for (int it = 0; it < 16; ++it) {
            int id = it * NT + tid;
            int r  = id >> 5;
            int c  = (id & 31) << 2;
            cpa16(dV + (u32)(r * VS + c) * 4u,
                  vb + (size_t)(kv0 + r) * Dd + c);
        }
        CP_COMMIT();

        // ---- S = Q@K^T via FFMA2 (prefetch-pipelined) ----
        u64 s2[4][4];
#pragma unroll
        for (int ip = 0; ip < 4; ++ip)
#pragma unroll
            for (int j = 0; j < 4; ++j) s2[ip][j] = 0ull;

        float4 kf_n = *(const float4*)(kPtr);
        ulonglong2 qv_n = *(const ulonglong2*)(qPtr);
        ulonglong2 qw_n = *(const ulonglong2*)(qPtr + 4);
#pragma unroll 4
        for (int d = 0; d < Dd; ++d) {
            float4 kf = kf_n;
            ulonglong2 qv = qv_n, qw = qw_n;
            // prefetch d+1 (over-read at d=127 lands in the next smem region; unused)
            kf_n = *(const float4*)(kPtr + (d + 1) * KS);
            qv_n = *(const ulonglong2*)(qPtr + (d + 1) * QS);
            qw_n = *(const ulonglong2*)(qPtr + (d + 1) * QS + 4);
            u64 q01 = qv.x, q23 = qv.y, q45 = qw.x, q67 = qw.y;
            u64 k0 = pk2(kf.x, kf.x), k1 = pk2(kf.y, kf.y);
            u64 k2 = pk2(kf.z, kf.z), k3 = pk2(kf.w, kf.w);
            s2[0][0] = ffma2(q01, k0, s2[0][0]);
            s2[0][1] = ffma2(q01, k1, s2[0][1]);
            s2[0][2] = ffma2(q01, k2, s2[0][2]);
            s2[0][3] = ffma2(q01, k3, s2[0][3]);
            s2[1][0] = ffma2(q23, k0, s2[1][0]);
            s2[1][1] = ffma2(q23, k1, s2[1][1]);
            s2[1][2] = ffma2(q23, k2, s2[1][2]);
            s2[1][3] = ffma2(q23, k3, s2[1][3]);
            s2[2][0] = ffma2(q45, k0, s2[2][0]);
            s2[2][1] = ffma2(q45, k1, s2[2][1]);
            s2[2][2] = ffma2(q45, k2, s2[2][2]);
            s2[2][3] = ffma2(q45, k3, s2[2][3]);
            s2[3][0] = ffma2(q67, k0, s2[3][0]);
            s2[3][1] = ffma2(q67, k1, s2[3][1]);
            s2[3][2] = ffma2(q67, k2, s2[3][2]);
            s2[3][3] = ffma2(q67, k3, s2[3][3]);
        }

        // ---- online softmax (m reduced per-iter; l lane-local) ----
        float p[8][4];
#pragma unroll
        for (int ip = 0; ip < 4; ++ip)
#pragma unroll
            for (int j = 0; j < 4; ++j)
                upk2(s2[ip][j], p[2 * ip][j], p[2 * ip + 1][j]);

        float fac[8];
#pragma unroll
        for (int i = 0; i < 8; ++i) {
            float mx = fmaxf(fmaxf(p[i][0], p[i][1]), fmaxf(p[i][2], p[i][3]));
#pragma unroll
            for (int off = 16; off >= 1; off >>= 1)
                mx = fmaxf(mx, __shfl_xor_sync(0xffffffffu, mx, off));
            float mnew = fmaxf(m_i[i], mx);
            fac[i] = __expf(m_i[i] - mnew);
            m_i[i] = mnew;
            float rs = 0.f;
#pragma unroll
            for (int j = 0; j < 4; ++j) {
                p[i][j] = __expf(p[i][j] - mnew);
                rs += p[i][j];
            }
            l_i[i] = l_i[i] * fac[i] + rs;      // lane-local partial
        }
#pragma unroll
        for (int ip = 0; ip < 4; ++ip) {
            u64 f2 = pk2(fac[2 * ip], fac[2 * ip + 1]);
#pragma unroll
            for (int j = 0; j < 4; ++j) acc[ip][j] = fmul2(acc[ip][j], f2);
        }

        // V(i) landed (only V(i) pending; K(i+1) not yet issued)
        CP_WAIT0();

        // ---- write masked P^T (apply keep bits) ----
#pragma unroll
        for (int j = 0; j < 4; ++j) {
            int c = (tn << 2) + j;
            float4 w0, w1;
            w0.x = (mbits >> (0 + j)) & 1u  ? p[0][j] : 0.f;
            w0.y = (mbits >> (4 + j)) & 1u  ? p[1][j] : 0.f;
            w0.z = (mbits >> (8 + j)) & 1u  ? p[2][j] : 0.f;
            w0.w = (mbits >> (12 + j)) & 1u ? p[3][j] : 0.f;
            w1.x = (mbits >> (16 + j)) & 1u ? p[4][j] : 0.f;
            w1.y = (mbits >> (20 + j)) & 1u ? p[5][j] : 0.f;
            w1.z = (mbits >> (24 + j)) & 1u ? p[6][j] : 0.f;
            w1.w = (mbits >> (28 + j)) & 1u ? p[7][j] : 0.f;
            *(float4*)(sPt + c * PS + (tm << 3)) = w0;
            *(float4*)(sPt + c * PS + (tm << 3) + 4) = w1;
        }
        __syncthreads();        // B: P + V visible; sKt QK reads done

        // issue K(i+1) into sKt (in flight during PV; waited at next top)
        if (kv0 + BN < SKV) {
#pragma unroll
            for (int it = 0; it < 16; ++it) {
                int id = it * NT + tid;
                int d  = id >> 5;
                int c  = (id & 31) << 2;
                cpa16(dK + (u32)(d * KS + c) * 4u,
                      ktb + (size_t)d * SKV + (kv0 + BN) + c);
            }
            CP_COMMIT();
        }

        // ---- acc += P^T' @ V via FFMA2 (prefetch-pipelined) ----
        ulonglong2 pA_n = *(const ulonglong2*)(pPtr);
        ulonglong2 pB_n = *(const ulonglong2*)(pPtr + 4);
        float4 vf_n = *(const float4*)(vPtr);
#pragma unroll 4
        for (int n = 0; n < BN; ++n) {
            ulonglong2 pA = pA_n, pB = pB_n;
            float4 vf = vf_n;
            // prefetch n+1 (over-read at n=127 covered by 512B tail pad)
            pA_n = *(const ulonglong2*)(pPtr + (n + 1) * PS);
            pB_n = *(const ulonglong2*)(pPtr + (n + 1) * PS + 4);
            vf_n = *(const float4*)(vPtr + (n + 1) * VS);
            u64 p01 = pA.x, p23 = pA.y, p45 = pB.x, p67 = pB.y;
            u64 v0 = pk2(vf.x, vf.x), v1 = pk2(vf.y, vf.y);
            u64 v2 = pk2(vf.z, vf.z), v3 = pk2(vf.w, vf.w);
            acc[0][0] = ffma2(p01, v0, acc[0][0]);
            acc[0][1] = ffma2(p01, v1, acc[0][1]);
            acc[0][2] = ffma2(p01, v2, acc[0][2]);
            acc[0][3] = ffma2(p01, v3, acc[0][3]);
            acc[1][0] = ffma2(p23, v0, acc[1][0]);
            acc[1][1] = ffma2(p23, v1, acc[1][1]);
            acc[1][2] = ffma2(p23, v2, acc[1][2]);
            acc[1][3] = ffma2(p23, v3, acc[1][3]);
            acc[2][0] = ffma2(p45, v0, acc[2][0]);
            acc[2][1] = ffma2(p45, v1, acc[2][1]);
            acc[2][2] = ffma2(p45, v2, acc[2][2]);
            acc[3][0] = ffma2(p67, v0, acc[3][0]);
            acc[2][3] = ffma2(p45, v3, acc[2][3]);
            acc[3][1] = ffma2(p67, v1, acc[3][1]);
            acc[3][2] = ffma2(p67, v2, acc[3][2]);
            acc[3][3] = ffma2(p67, v3, acc[3][3]);
        }
    }

    // ---- epilogue: reduce l across lanes, out = acc / (l * 0.7) ----
    float lr[8];
#pragma unroll
    for (int i = 0; i < 8; ++i) {
        float s = l_i[i];
#pragma unroll
        for (int off = 16; off >= 1; off >>= 1)
            s += __shfl_xor_sync(0xffffffffu, s, off);
        lr[i] = s;
    }
#pragma unroll
    for (int ip = 0; ip < 4; ++ip) {
        float inv0 = 1.0f / (lr[2 * ip] * 0.7f);
        float inv1 = 1.0f / (lr[2 * ip + 1] * 0.7f);
        float lo[4], hi[4];
#pragma unroll
        for (int j = 0; j < 4; ++j) upk2(acc[ip][j], lo[j], hi[j]);
        int r0 = q0 + (tm << 3) + 2 * ip;
        float* o0 = out + ((size_t)b * SQ + r0) * Dd + (tn << 2);
        float* o1 = o0 + Dd;
        *(float4*)o0 = make_float4(lo[0] * inv0, lo[1] * inv0, lo[2] * inv0, lo[3] * inv0);
        *(float4*)o1 = make_float4(hi[0] * inv1, hi[1] * inv1, hi[2] * inv1, hi[3] * inv1);
    }
}

// ---------------------------------------------------------------------------
extern "C" void kernel_launch(void* const* d_in, const int* in_sizes, int n_in,
                              void* d_out, int out_size) {
    const float* q  = (const float*)d_in[0];
    const float* k  = (const float*)d_in[1];
    const float* v  = (const float*)d_in[2];
    const float* sf = (const float*)d_in[3];
    float* out = (float*)d_out;

    // 1) fused prep: dropout keep-words (alu) + K transpose (DRAM), overlapped
    prep_kernel<<<MASK_BLOCKS + TPOSE_BLOCKS, 256>>>(k);

    // 2) Flash attention (+512B tail pad covers the PV prefetch over-read)
    size_t smem_bytes = (size_t)(Dd * QS + Dd * KS + BN * VS + BN * PS) * 4 + 512;
    cudaFuncSetAttribute(attn_kernel, cudaFuncAttributeMaxDynamicSharedMemorySize,
                         (int)smem_bytes);
    dim3 grid(SQ / BM, Bz);
    attn_kernel<<<grid, NT, smem_bytes>>>(q, v, sf, out);
}